// round 17
// baseline (speedup 1.0000x reference)
#include <cuda_runtime.h>
#include <cuda_fp16.h>

// ---------------------------------------------------------------------------
// MAHGN R17: merged tagged CSR per destination group. One contiguous in-edge
// segment per user/article node with (q<<20|global_row) entries; per-type
// softmax accumulators held in registers. GEMM/ad kernels = R16.
// ---------------------------------------------------------------------------

#define NU 200000
#define NA 100000
#define NC 500
#define DD 64
#define MAXE 4400000
#define TOTROWS 1001000

#define GEMM_SMEM (16384 + 33280)

__constant__ int gb_cum[9]   = {0, 1563, 2345, 3908, 5471, 6253, 6257, 7820, 7824};
__constant__ int gb_src[8]   = {0, 1, 0, 0, 1, 2, 0, 2};
__constant__ int gb_n[8]     = {NU, NA, NU, NU, NA, NC, NU, NC};
__constant__ int gb_hsoff[8] = {0, 200000, 300000, 500000, 700000, 800000, 800500, 1000500};
#define GEMM_BLOCKS 7824

// combined-CSR constants: group (0=U,1=A,2=C4,3=C6), q tag, hs slice offset
__constant__ int cg_grp[8] = {1, 0, 0, 0, 2, 1, 3, 0};
__constant__ int cg_q[8]   = {0, 0, 1, 2, 0, 1, 0, 3};
__constant__ int cg_hs[8]  = {0, 200000, 300000, 500000, 700000, 800000, 800500, 1000500};
// scan segments: U(196 blocks), A(98), C4(1), C6(1)
__constant__ int cb_boff[4] = {0, 196, 294, 295};
__constant__ int cb_nd[4]   = {NU, NA, NC, NC};
#define NBLK_SCANC 296

// features / accumulators
__device__ float  g_xu[NU*DD], g_xa[NA*DD], g_xc[NC*DD];
__device__ __half g_hsA[(size_t)TOTROWS*DD];
__device__ float  g_asA[TOTROWS*4];
__device__ float  g_adA[1000000*4];
__device__ float  g_adc4[NC*4], g_adc6[NC*4];
__device__ float  g_accu[NU*DD], g_acci[NA*DD];
__device__ float  g_tmpc0[NC*DD], g_tmpc1[NC*DD], g_denc0[NC*4], g_denc1[NC*4];

// combined CSR scratch
__device__ int g_cntU[NU], g_cntA[NA], g_cnt4[NC], g_cnt6[NC];
__device__ int g_curU[NU], g_curA[NA], g_cur4[NC], g_cur6[NC];
__device__ int g_ipU[NU+1], g_ipA[NA+1], g_ip4[NC+1], g_ip6[NC+1];
__device__ int g_bsum[512];
__device__ int g_rowsC[MAXE];

__device__ __forceinline__ float* xp(int s){ return s==0 ? g_xu : (s==1 ? g_xa : g_xc); }

// ---- packed f32x2 helpers ----
__device__ __forceinline__ unsigned long long pk2(float lo, float hi){
    unsigned long long r;
    asm("mov.b64 %0, {%1,%2};" : "=l"(r) : "f"(lo), "f"(hi));
    return r;
}
__device__ __forceinline__ void upk2(unsigned long long v, float& lo, float& hi){
    asm("mov.b64 {%0,%1}, %2;" : "=f"(lo), "=f"(hi) : "l"(v));
}
__device__ __forceinline__ void fma2(unsigned long long& c,
                                     unsigned long long a, unsigned long long b){
    asm("fma.rn.f32x2 %0, %1, %2, %3;" : "=l"(c) : "l"(a), "l"(b), "l"(c));
}

// ---------------------------------------------------------------------------
__global__ void k_init(const float* __restrict__ xu, const float* __restrict__ xa,
                       const float* __restrict__ xc){
    int i = blockIdx.x * blockDim.x + threadIdx.x;
    if (i < NU) g_cntU[i] = 0;
    else if (i < NU+NA) g_cntA[i-NU] = 0;
    else if (i < NU+NA+NC) g_cnt4[i-NU-NA] = 0;
    else if (i < NU+NA+2*NC) g_cnt6[i-NU-NA-NC] = 0;
    if (i < NU*DD){
        float v = xu[i]; g_xu[i] = v; g_accu[i] = v;
    } else if (i < (NU+NA)*DD){
        int j = i - NU*DD;
        float v = xa[j]; g_xa[j] = v; g_acci[j] = v;
    } else if (i < (NU+NA+NC)*DD){
        int j = i - (NU+NA)*DD;
        g_xc[j] = xc[j];
    }
}

// ---------------------------------------------------------------------------
// combined CSR build
// ---------------------------------------------------------------------------
#define PICK_TYPE \
    const int* ei; int base, next, t; \
    if      (i < c1){ ei = e0; base = 0;  next = c1; t = 0; } \
    else if (i < c2){ ei = e1; base = c1; next = c2; t = 1; } \
    else if (i < c3){ ei = e2; base = c2; next = c3; t = 2; } \
    else if (i < c4){ ei = e3; base = c3; next = c4; t = 3; } \
    else if (i < c5){ ei = e4; base = c4; next = c5; t = 4; } \
    else if (i < c6){ ei = e5; base = c5; next = c6; t = 5; } \
    else if (i < c7){ ei = e6; base = c6; next = c7; t = 6; } \
    else            { ei = e7; base = c7; next = cT; t = 7; } \
    int E = next - base, local = i - base;

__global__ void k_count_all(const int* e0,const int* e1,const int* e2,const int* e3,
                            const int* e4,const int* e5,const int* e6,const int* e7,
                            int c1,int c2,int c3,int c4,int c5,int c6,int c7,int cT){
    int i = blockIdx.x * blockDim.x + threadIdx.x;
    if (i >= cT) return;
    PICK_TYPE
    int col = ei[E + local];
    int grp = cg_grp[t];
    if      (grp == 0) atomicAdd(&g_cntU[col], 1);
    else if (grp == 1) atomicAdd(&g_cntA[col], 1);
    else if (grp == 2) atomicAdd(&g_cnt4[col], 1);
    else               atomicAdd(&g_cnt6[col], 1);
}

__global__ void k_scan1(){
    __shared__ int wsum[32];
    int b = blockIdx.x, tid = threadIdx.x, lane = tid & 31, wid = tid >> 5;
    int s;
    if      (b < 196) s = 0;
    else if (b < 294) s = 1;
    else if (b < 295) s = 2;
    else              s = 3;
    int i = (b - cb_boff[s]) * 1024 + tid;
    int nd = cb_nd[s];
    const int* cnt = (s==0) ? g_cntU : (s==1) ? g_cntA : (s==2) ? g_cnt4 : g_cnt6;
    int*       ip  = (s==0) ? g_ipU  : (s==1) ? g_ipA  : (s==2) ? g_ip4  : g_ip6;
    int v = (i < nd) ? cnt[i] : 0;
    int x = v;
#pragma unroll
    for (int o = 1; o < 32; o <<= 1){
        int y = __shfl_up_sync(0xffffffffu, x, o);
        if (lane >= o) x += y;
    }
    if (lane == 31) wsum[wid] = x;
    __syncthreads();
    if (wid == 0){
        int ss = wsum[lane];
#pragma unroll
        for (int o = 1; o < 32; o <<= 1){
            int y = __shfl_up_sync(0xffffffffu, ss, o);
            if (lane >= o) ss += y;
        }
        wsum[lane] = ss;
    }
    __syncthreads();
    int excl = (x - v) + (wid ? wsum[wid - 1] : 0);
    if (i < nd) ip[i] = excl;
    if (tid == 0) g_bsum[b] = wsum[31];
}

__global__ void k_scan2(){
    int w = threadIdx.x >> 5, lane = threadIdx.x & 31;
    if (w >= 4) return;
    const int nbs[4] = {196, 98, 1, 1};
    int off = cb_boff[w], nb = nbs[w];
    int carry = 0;
    for (int base = 0; base < nb; base += 32){
        int i = base + lane;
        int v = (i < nb) ? g_bsum[off + i] : 0;
        int x = v;
#pragma unroll
        for (int o = 1; o < 32; o <<= 1){
            int y = __shfl_up_sync(0xffffffffu, x, o);
            if (lane >= o) x += y;
        }
        if (i < nb) g_bsum[off + i] = x - v + carry;
        carry += __shfl_sync(0xffffffffu, x, 31);
    }
}

__global__ void k_scan3(int EU, int EA, int E4, int E6){
    int j = blockIdx.x * blockDim.x + threadIdx.x;
    int s, jj = j;
    if (jj < NU+1)      { s = 0; }
    else { jj -= NU+1;
        if (jj < NA+1)  { s = 1; }
        else { jj -= NA+1;
            if (jj < NC+1) { s = 2; }
            else { jj -= NC+1;
                if (jj < NC+1) s = 3; else return;
            }
        }
    }
    int nd = cb_nd[s];
    int* ip  = (s==0) ? g_ipU  : (s==1) ? g_ipA  : (s==2) ? g_ip4  : g_ip6;
    int* cur = (s==0) ? g_curU : (s==1) ? g_curA : (s==2) ? g_cur4 : g_cur6;
    if (jj < nd){
        int v = ip[jj] + g_bsum[cb_boff[s] + (jj >> 10)];
        ip[jj] = v;
        cur[jj] = v;
    } else if (jj == nd){
        const int es[4] = {EU, EA, E4, E6};
        ip[nd] = es[s];
    }
}

__global__ void k_fill_all(const int* e0,const int* e1,const int* e2,const int* e3,
                           const int* e4,const int* e5,const int* e6,const int* e7,
                           int c1,int c2,int c3,int c4,int c5,int c6,int c7,int cT,
                           int bA, int b4, int b6){
    int i = blockIdx.x * blockDim.x + threadIdx.x;
    if (i >= cT) return;
    PICK_TYPE
    int row = ei[local];
    int col = ei[E + local];
    int val = (cg_q[t] << 20) | (cg_hs[t] + row);
    int grp = cg_grp[t];
    if (grp == 0){
        int pos = atomicAdd(&g_curU[col], 1);
        g_rowsC[pos] = val;
    } else if (grp == 1){
        int pos = atomicAdd(&g_curA[col], 1);
        g_rowsC[bA + pos] = val;
    } else if (grp == 2){
        int pos = atomicAdd(&g_cur4[col], 1);
        g_rowsC[b4 + pos] = val;
    } else {
        int pos = atomicAdd(&g_cur6[col], 1);
        g_rowsC[b6 + pos] = val;
    }
}

// ---------------------------------------------------------------------------
// Batched GEMM (R16-proven; f32x2 inner loop, zero-mov W pairs)
// ---------------------------------------------------------------------------
__global__ void __launch_bounds__(256, 4)
k_gemm_all(const float* __restrict__ Wsrc,
           const float* __restrict__ att_src, int l){
    extern __shared__ float dsm[];
    float* sW = dsm;
    float* sX = dsm + 4096;
    int b = blockIdx.x;
    int t = 0;
#pragma unroll
    for (int q = 1; q < 8; q++) if (b >= gb_cum[q]) t = q;
    int src_sel = gb_src[t];
    int N = gb_n[t];
    const float* x = xp(src_sel);
    const float* W   = Wsrc    + (size_t)(l*8 + t) * 4096;
    const float* att = att_src + (size_t)(l*8 + t) * 64;
    __half* hs = g_hsA + (size_t)gb_hsoff[t] * 64;
    float*  as = g_asA + (size_t)gb_hsoff[t] * 4;
    int tid = threadIdx.x;

    for (int i = tid; i < 1024; i += 256)
        ((float4*)sW)[i] = ((const float4*)W)[i];

    int row0 = (b - gb_cum[t]) * 128;
    for (int i = tid; i < 2048; i += 256){
        int r = i >> 4, c4 = i & 15;
        int gr = row0 + r;
        float4 v = (gr < N) ? ((const float4*)x)[(size_t)gr*16 + c4]
                            : make_float4(0.f, 0.f, 0.f, 0.f);
        sX[r*65 + c4*4+0] = v.x; sX[r*65 + c4*4+1] = v.y;
        sX[r*65 + c4*4+2] = v.z; sX[r*65 + c4*4+3] = v.w;
    }
    __syncthreads();

    int rp = tid >> 3, cg = tid & 7;
    int r0 = rp * 4;
    int cA = cg * 4, cB = 32 + cg * 4;
    float4 attA = __ldg((const float4*)&att[cA]);
    float4 attB = __ldg((const float4*)&att[cB]);

    unsigned long long acc2[4][4];
#pragma unroll
    for (int i = 0; i < 4; i++)
#pragma unroll
        for (int p = 0; p < 4; p++) acc2[i][p] = 0ULL;

#pragma unroll 8
    for (int k = 0; k < 64; k++){
        ulonglong2 wA = *(const ulonglong2*)&sW[k*64 + cA];
        ulonglong2 wB = *(const ulonglong2*)&sW[k*64 + cB];
#pragma unroll
        for (int i = 0; i < 4; i++){
            float xv = sX[(r0 + i)*65 + k];
            unsigned long long xv2 = pk2(xv, xv);
            fma2(acc2[i][0], xv2, wA.x);
            fma2(acc2[i][1], xv2, wA.y);
            fma2(acc2[i][2], xv2, wB.x);
            fma2(acc2[i][3], xv2, wB.y);
        }
    }

#pragma unroll
    for (int i = 0; i < 4; i++){
        float a0,a1,a2,a3,a4,a5,a6,a7;
        upk2(acc2[i][0], a0, a1);
        upk2(acc2[i][1], a2, a3);
        upk2(acc2[i][2], a4, a5);
        upk2(acc2[i][3], a6, a7);
        int gr = row0 + r0 + i;
        float pA = a0*attA.x + a1*attA.y + a2*attA.z + a3*attA.w;
        float pB = a4*attB.x + a5*attB.y + a6*attB.z + a7*attB.w;
        pA += __shfl_xor_sync(0xffffffffu, pA, 1);
        pA += __shfl_xor_sync(0xffffffffu, pA, 2);
        pB += __shfl_xor_sync(0xffffffffu, pB, 1);
        pB += __shfl_xor_sync(0xffffffffu, pB, 2);
        if (gr < N){
            union { __half2 h2[2]; uint2 u; } pk;
            pk.h2[0] = __floats2half2_rn(a0, a1);
            pk.h2[1] = __floats2half2_rn(a2, a3);
            *(uint2*)&hs[(size_t)gr*64 + cA] = pk.u;
            pk.h2[0] = __floats2half2_rn(a4, a5);
            pk.h2[1] = __floats2half2_rn(a6, a7);
            *(uint2*)&hs[(size_t)gr*64 + cB] = pk.u;
            if ((cg & 3) == 0){
                int h01 = cg >> 2;
                as[gr*4 + h01]     = pA;
                as[gr*4 + 2 + h01] = pB;
            }
        }
    }
}

// ---------------------------------------------------------------------------
// merged a_d (R16-proven)
// ---------------------------------------------------------------------------
__global__ void k_ad_all(const float* __restrict__ Wdst,
                         const float* __restrict__ attd, int l){
    __shared__ float sWd[4][64][4];
    __shared__ float sX[64][65];
    int b = blockIdx.x;
    int dst_sel, N, nT, row0;
    int tl[4], dofs[4];
    if (b < 3125){
        dst_sel = 0; N = NU; nT = 4; row0 = b * 64;
        tl[0]=1; tl[1]=2; tl[2]=3; tl[3]=7;
        dofs[0]=100000; dofs[1]=300000; dofs[2]=500000; dofs[3]=800000;
    } else {
        dst_sel = 1; N = NA; nT = 2; row0 = (b - 3125) * 64;
        tl[0]=0; tl[1]=5; tl[2]=0; tl[3]=0;
        dofs[0]=0; dofs[1]=700000; dofs[2]=0; dofs[3]=0;
    }
    const float* x = xp(dst_sel);
    int tid = threadIdx.x;

    {
        int k = tid >> 2, h = tid & 3;
#pragma unroll
        for (int q = 0; q < 4; q++){
            if (q < nT){
                const float* Wd = Wdst + (size_t)(l*8 + tl[q]) * 4096;
                const float* at = attd + (size_t)(l*8 + tl[q]) * 64;
                float s = 0.f;
#pragma unroll
                for (int c = 0; c < 16; c++) s += Wd[k*64 + h*16 + c] * at[h*16 + c];
                sWd[q][k][h] = s;
            }
        }
    }
    for (int i = tid; i < 4096; i += 256){
        int r = i >> 6, c = i & 63;
        int gr = row0 + r;
        sX[r][c] = (gr < N) ? x[gr*64 + c] : 0.f;
    }
    __syncthreads();

    int r = tid >> 2, h = tid & 3;
    int gr = row0 + r;
    if (gr < N){
#pragma unroll
        for (int q = 0; q < 4; q++){
            if (q < nT){
                float s = 0.f;
#pragma unroll
                for (int k = 0; k < 64; k++) s += sX[r][k] * sWd[q][k][h];
                g_adA[(size_t)(dofs[q] + gr)*4 + h] = s;
            }
        }
    }
}

// ---------------------------------------------------------------------------
// merged cat a_d (R16-proven)
// ---------------------------------------------------------------------------
__global__ void k_ad_cat(const float* __restrict__ Wdst,
                         const float* __restrict__ attd, int l){
    __shared__ float sWd[2][64][4];
    __shared__ float sX[64][65];
    int tid = threadIdx.x;
    const int tl[2] = {4, 6};
    {
        int k = tid >> 2, h = tid & 3;
#pragma unroll
        for (int q = 0; q < 2; q++){
            const float* Wd = Wdst + (size_t)(l*8 + tl[q]) * 4096;
            const float* at = attd + (size_t)(l*8 + tl[q]) * 64;
            float s = 0.f;
#pragma unroll
            for (int c = 0; c < 16; c++) s += Wd[k*64 + h*16 + c] * at[h*16 + c];
            sWd[q][k][h] = s;
        }
    }
    int row0 = blockIdx.x * 64;
    for (int i = tid; i < 4096; i += 256){
        int r = i >> 6, c = i & 63;
        int gr = row0 + r;
        sX[r][c] = (gr < NC) ? g_xc[gr*64 + c] : 0.f;
    }
    __syncthreads();

    int r = tid >> 2, h = tid & 3;
    int gr = row0 + r;
    if (gr < NC){
        float s4 = 0.f, s6 = 0.f;
#pragma unroll
        for (int k = 0; k < 64; k++){
            float xv = sX[r][k];
            s4 += xv * sWd[0][k][h];
            s6 += xv * sWd[1][k][h];
        }
        g_adc4[gr*4 + h] = s4;
        g_adc6[gr*4 + h] = s6;
        g_denc0[gr*4 + h] = 0.f;
        g_denc1[gr*4 + h] = 0.f;
        float4 z = make_float4(0.f,0.f,0.f,0.f);
        float4* t0 = (float4*)&g_tmpc0[gr*64 + h*16];
        float4* t1 = (float4*)&g_tmpc1[gr*64 + h*16];
        t0[0]=z; t0[1]=z; t0[2]=z; t0[3]=z;
        t1[0]=z; t1[1]=z; t1[2]=z; t1[3]=z;
    }
}

// ---------------------------------------------------------------------------
// merged aggregation: one contiguous tagged segment per node.
// lane owns cols {2l,2l+1}, head h = lane>>3.
// ---------------------------------------------------------------------------
#define PROC_U(vv) { \
    int q_ = (vv) >> 20, g_ = (vv) & 0xFFFFF; \
    float s_ = __ldg(&g_asA[(size_t)g_*4 + h]); \
    __half2 u_ = __ldg(&hs2[(size_t)g_*32 + lane]); \
    float ad_ = q_==0 ? ad0 : (q_==1 ? ad1 : (q_==2 ? ad2 : ad3)); \
    float ev_ = s_ + ad_; ev_ = ev_ > 0.f ? ev_ : 0.2f*ev_; \
    float ex_ = __expf(ev_); \
    float2 f_ = __half22float2(u_); \
    if (q_==0){ a00 += ex_*f_.x; a01 += ex_*f_.y; d0 += ex_; } \
    else if (q_==1){ a10 += ex_*f_.x; a11 += ex_*f_.y; d1 += ex_; } \
    else if (q_==2){ a20 += ex_*f_.x; a21 += ex_*f_.y; d2 += ex_; } \
    else { a30 += ex_*f_.x; a31 += ex_*f_.y; d3 += ex_; } }

#define PROC_A(vv) { \
    int q_ = (vv) >> 20, g_ = (vv) & 0xFFFFF; \
    float s_ = __ldg(&g_asA[(size_t)g_*4 + h]); \
    __half2 u_ = __ldg(&hs2[(size_t)g_*32 + lane]); \
    float ad_ = q_ == 0 ? ad0 : ad1; \
    float ev_ = s_ + ad_; ev_ = ev_ > 0.f ? ev_ : 0.2f*ev_; \
    float ex_ = __expf(ev_); \
    float2 f_ = __half22float2(u_); \
    if (q_==0){ a00 += ex_*f_.x; a01 += ex_*f_.y; d0 += ex_; } \
    else { a10 += ex_*f_.x; a11 += ex_*f_.y; d1 += ex_; } }

__global__ void k_aggr_all(int bA, const float* __restrict__ bias, int l){
    int gwid = (blockIdx.x * blockDim.x + threadIdx.x) >> 5;
    int lane = threadIdx.x & 31, h = lane >> 3;
    int c0 = 2*lane, c1 = 2*lane + 1;
    const float* bl = bias + l*512;
    const __half2* hs2 = (const __half2*)g_hsA;
    const float eps = 1e-16f;

    if (gwid < NU){
        int gw = gwid;
        int beg = g_ipU[gw], end = g_ipU[gw + 1];
        float ad0 = g_adA[(size_t)(100000 + gw)*4 + h];
        float ad1 = g_adA[(size_t)(300000 + gw)*4 + h];
        float ad2 = g_adA[(size_t)(500000 + gw)*4 + h];
        float ad3 = g_adA[(size_t)(800000 + gw)*4 + h];
        float a00=0.f,a01=0.f,d0=0.f, a10=0.f,a11=0.f,d1=0.f;
        float a20=0.f,a21=0.f,d2=0.f, a30=0.f,a31=0.f,d3=0.f;
        const int* rows = g_rowsC;   // user region base 0
        int e = beg;
        for (; e + 4 <= end; e += 4){
            int v0 = __ldg(rows + e + 0), v1 = __ldg(rows + e + 1);
            int v2 = __ldg(rows + e + 2), v3 = __ldg(rows + e + 3);
            PROC_U(v0) PROC_U(v1) PROC_U(v2) PROC_U(v3)
        }
        for (; e < end; e++){ int v = __ldg(rows + e); PROC_U(v) }

        float o0 = bl[64+c0] + bl[128+c0] + bl[192+c0] + bl[448+c0]
                 + a00/(d0+eps) + a10/(d1+eps) + a20/(d2+eps) + a30/(d3+eps);
        float o1 = bl[64+c1] + bl[128+c1] + bl[192+c1] + bl[448+c1]
                 + a01/(d0+eps) + a11/(d1+eps) + a21/(d2+eps) + a31/(d3+eps);
        float w0 = o0 > 0.f ? o0 : 0.01f*o0;
        float w1 = o1 > 0.f ? o1 : 0.01f*o1;
        *(float2*)&g_xu[(size_t)gw*64 + c0] = make_float2(w0, w1);
        float2 au = *(float2*)&g_accu[(size_t)gw*64 + c0];
        au.x += w0; au.y += w1;
        *(float2*)&g_accu[(size_t)gw*64 + c0] = au;
    } else if (gwid < NU + NA){
        int gw = gwid - NU;
        int beg = g_ipA[gw], end = g_ipA[gw + 1];
        float ad0 = g_adA[(size_t)(0      + gw)*4 + h];
        float ad1 = g_adA[(size_t)(700000 + gw)*4 + h];
        float a00=0.f,a01=0.f,d0=0.f, a10=0.f,a11=0.f,d1=0.f;
        const int* rows = g_rowsC + bA;
        int e = beg;
        for (; e + 4 <= end; e += 4){
            int v0 = __ldg(rows + e + 0), v1 = __ldg(rows + e + 1);
            int v2 = __ldg(rows + e + 2), v3 = __ldg(rows + e + 3);
            PROC_A(v0) PROC_A(v1) PROC_A(v2) PROC_A(v3)
        }
        for (; e < end; e++){ int v = __ldg(rows + e); PROC_A(v) }

        float o0 = bl[0+c0] + bl[320+c0] + a00/(d0+eps) + a10/(d1+eps);
        float o1 = bl[0+c1] + bl[320+c1] + a01/(d0+eps) + a11/(d1+eps);
        float w0 = o0 > 0.f ? o0 : 0.01f*o0;
        float w1 = o1 > 0.f ? o1 : 0.01f*o1;
        *(float2*)&g_xa[(size_t)gw*64 + c0] = make_float2(w0, w1);
        float2 au = *(float2*)&g_acci[(size_t)gw*64 + c0];
        au.x += w0; au.y += w1;
        *(float2*)&g_acci[(size_t)gw*64 + c0] = au;
    }
}

// ---------------------------------------------------------------------------
// category aggregation: entries are global rows (untagged q=0)
// ---------------------------------------------------------------------------
#define CCHUNK 64
__device__ __forceinline__ void do_edges_cat(const int* __restrict__ rows, int beg, int end,
                                             int lane, int h, float adh,
                                             float& a0, float& a1, float& d){
    const __half2* hs2 = (const __half2*)g_hsA;
    int e = beg;
    for (; e + 4 <= end; e += 4){
        int r0 = __ldg(rows + e + 0), r1 = __ldg(rows + e + 1);
        int r2 = __ldg(rows + e + 2), r3 = __ldg(rows + e + 3);
        float s0 = __ldg(&g_asA[(size_t)r0*4 + h]);
        float s1 = __ldg(&g_asA[(size_t)r1*4 + h]);
        float s2 = __ldg(&g_asA[(size_t)r2*4 + h]);
        float s3 = __ldg(&g_asA[(size_t)r3*4 + h]);
        __half2 u0 = __ldg(&hs2[(size_t)r0*32 + lane]);
        __half2 u1 = __ldg(&hs2[(size_t)r1*32 + lane]);
        __half2 u2 = __ldg(&hs2[(size_t)r2*32 + lane]);
        __half2 u3 = __ldg(&hs2[(size_t)r3*32 + lane]);

        float e0 = s0 + adh, e1 = s1 + adh, e2 = s2 + adh, e3 = s3 + adh;
        e0 = e0 > 0.f ? e0 : 0.2f*e0;
        e1 = e1 > 0.f ? e1 : 0.2f*e1;
        e2 = e2 > 0.f ? e2 : 0.2f*e2;
        e3 = e3 > 0.f ? e3 : 0.2f*e3;
        float x0 = __expf(e0), x1 = __expf(e1), x2 = __expf(e2), x3 = __expf(e3);

        float2 f0 = __half22float2(u0);
        float2 f1 = __half22float2(u1);
        float2 f2 = __half22float2(u2);
        float2 f3 = __half22float2(u3);
        a0 += x0*f0.x + x1*f1.x + x2*f2.x + x3*f3.x;
        a1 += x0*f0.y + x1*f1.y + x2*f2.y + x3*f3.y;
        d  += x0 + x1 + x2 + x3;
    }
    for (; e < end; e++){
        int row = __ldg(rows + e);
        float ev = __ldg(&g_asA[(size_t)row*4 + h]) + adh;
        ev = ev > 0.f ? ev : 0.2f*ev;
        float ex = __expf(ev);
        float2 f = __half22float2(__ldg(&hs2[(size_t)row*32 + lane]));
        a0 += ex*f.x; a1 += ex*f.y; d += ex;
    }
}

__device__ __forceinline__ void cat_chunks(const int* __restrict__ ip,
                                           const int* __restrict__ rows, int E,
                                           const float* __restrict__ adc,
                                           float* __restrict__ tmpc,
                                           float* __restrict__ denc,
                                           int w, int lane){
    int es = w * CCHUNK;
    if (es >= E) return;
    int ee = min(es + CCHUNK, E);
    int lo = 0, hi = NC;
    while (lo < hi){
        int mid = (lo + hi + 1) >> 1;
        if (ip[mid] <= es) lo = mid; else hi = mid - 1;
    }
    int n = lo;
    int h = lane >> 3;
    int c0 = 2*lane;

    while (es < ee){
        int segend = min(ip[n + 1], ee);
        float adh = adc[n*4 + h];
        float a0 = 0.f, a1 = 0.f, d = 0.f;
        do_edges_cat(rows, es, segend, lane, h, adh, a0, a1, d);
        atomicAdd(&tmpc[n*64 + c0],     a0);
        atomicAdd(&tmpc[n*64 + c0 + 1], a1);
        if ((lane & 7) == 0)
            atomicAdd(&denc[n*4 + h], d);
        es = segend;
        n++;
    }
}

__global__ void k_aggr_cat_all(int b4, int E4, int b6, int E6){
    int w = (blockIdx.x * blockDim.x + threadIdx.x) >> 5;
    int lane = threadIdx.x & 31;
    int ch4 = (E4 + CCHUNK - 1) / CCHUNK;
    if (w < ch4){
        cat_chunks(g_ip4, g_rowsC + b4, E4, g_adc4, g_tmpc0, g_denc0, w, lane);
    } else {
        cat_chunks(g_ip6, g_rowsC + b6, E6, g_adc6, g_tmpc1, g_denc1, w - ch4, lane);
    }
}

__global__ void k_cat_final(const float* __restrict__ bias, int l){
    int i = blockIdx.x * blockDim.x + threadIdx.x;
    if (i >= NC*DD) return;
    int n = i >> 6, c = i & 63, h = c >> 4;
    const float* bl = bias + l*512;
    float v = g_tmpc0[i] / (g_denc0[n*4 + h] + 1e-16f)
            + g_tmpc1[i] / (g_denc1[n*4 + h] + 1e-16f)
            + bl[256 + c] + bl[384 + c];
    g_xc[i] = v > 0.f ? v : 0.01f*v;
}

// ---------------------------------------------------------------------------
__global__ void k_final(float* __restrict__ out){
    int i = blockIdx.x * blockDim.x + threadIdx.x;
    const int nu = NU * DD;
    const int tot = nu + NA * DD;
    if (i >= tot) return;
    const float s = 1.f / 3.f;
    out[i] = (i < nu) ? g_accu[i] * s : g_acci[i - nu] * s;
}

// ---------------------------------------------------------------------------
static inline int cdiv(long long a, int b){ return (int)((a + b - 1) / b); }

extern "C" void kernel_launch(void* const* d_in, const int* in_sizes, int n_in,
                              void* d_out, int out_size){
    const float* x_user    = (const float*)d_in[0];
    const float* x_article = (const float*)d_in[1];
    const float* x_cat     = (const float*)d_in[2];
    const float* Wsrc      = (const float*)d_in[3];
    const float* Wdst      = (const float*)d_in[4];
    const float* att_src   = (const float*)d_in[5];
    const float* att_dst   = (const float*)d_in[6];
    const float* bias      = (const float*)d_in[7];
    float* out = (float*)d_out;

    cudaFuncSetAttribute(k_gemm_all, cudaFuncAttributeMaxDynamicSharedMemorySize, GEMM_SMEM);

    int EN[8], CUM[9]; CUM[0] = 0;
    for (int t = 0; t < 8; t++){ EN[t] = in_sizes[8 + t] / 2; CUM[t+1] = CUM[t] + EN[t]; }
    const int* EP[8];
    for (int t = 0; t < 8; t++) EP[t] = (const int*)d_in[8 + t];

    // combined region sizes / bases
    const int EU = EN[1] + EN[2] + EN[3] + EN[7];
    const int EA = EN[0] + EN[5];
    const int bA = EU, b4 = EU + EA, b6 = EU + EA + EN[4];

    const int TOTN = (NU + NA + NC) * DD;
    const int SCAN3N = (NU+1) + (NA+1) + 2*(NC+1);

    k_init     <<<cdiv(TOTN, 256), 256>>>(x_user, x_article, x_cat);
    k_count_all<<<cdiv(CUM[8], 256), 256>>>(EP[0],EP[1],EP[2],EP[3],EP[4],EP[5],EP[6],EP[7],
                                            CUM[1],CUM[2],CUM[3],CUM[4],CUM[5],CUM[6],CUM[7],CUM[8]);
    k_scan1    <<<NBLK_SCANC, 1024>>>();
    // #4 PROFILED: batched layer-0 GEMM
    k_gemm_all <<<GEMM_BLOCKS, 256, GEMM_SMEM>>>(Wsrc, att_src, 0);
    k_scan2    <<<1, 128>>>();
    k_scan3    <<<cdiv(SCAN3N, 256), 256>>>(EU, EA, EN[4], EN[6]);
    k_fill_all <<<cdiv(CUM[8], 256), 256>>>(EP[0],EP[1],EP[2],EP[3],EP[4],EP[5],EP[6],EP[7],
                                            CUM[1],CUM[2],CUM[3],CUM[4],CUM[5],CUM[6],CUM[7],CUM[8],
                                            bA, b4, b6);

    for (int l = 0; l < 2; l++){
        if (l > 0)
            k_gemm_all<<<GEMM_BLOCKS, 256, GEMM_SMEM>>>(Wsrc, att_src, l);
        k_ad_all <<<3125 + 1563, 256>>>(Wdst, att_dst, l);
        k_ad_cat <<<cdiv(NC, 64), 256>>>(Wdst, att_dst, l);
        k_aggr_all<<<cdiv(NU + NA, 8), 256>>>(bA, bias, l);
        {
            int ch = cdiv(EN[4], CCHUNK) + cdiv(EN[6], CCHUNK);
            k_aggr_cat_all<<<cdiv(ch, 8), 256>>>(b4, EN[4], b6, EN[6]);
        }
        k_cat_final<<<cdiv(NC*DD, 256), 256>>>(bias, l);
    }

    k_final<<<cdiv((long long)(NU + NA) * DD, 256), 256>>>(out);
}